// round 9
// baseline (speedup 1.0000x reference)
#include <cuda_runtime.h>
#include <cuda_bf16.h>
#include <math_constants.h>
#include <cstdint>

// Problem constants
#define NB   16
#define NC   1024
#define NT   16
#define NP   360          // H*W = 12*30
#define NK   120          // top-k
#define ROWS 482          // 1 + 120 + 1 + 360
#define CSPLIT 64
#define CCHUNK (NC / CSPLIT)        // 16 c per score block
#define TSTRIDE ((size_t)NT * NP)   // 5760 floats between consecutive c

// Phase-1 block roles (bid order: producers before consumers -> no deadlock)
#define N_SCORE  1024                 // 16 b x 64 cs
#define N_COPY1  1536                 // 32 ct x 3 pt x 16 b
#define BID_COPY1  N_SCORE
#define BID_SORT   (N_SCORE + N_COPY1)
#define GRID_P1    (BID_SORT + NB)

// Scratch (no device allocation allowed -> __device__ globals)
__device__ __align__(16) float g_spart[NB][CSPLIT][NP];   // 1.5 MB
__device__ int g_posmap[NB][NP];
__device__ int g_cnt[NB * 32];   // per-b score-block counters (128B padded), init 0

// ---------------------------------------------------------------------------
// Phase 1: scores (cp.async staging) | frame-1 transpose copy | per-b sort.
// Sort blocks are dispatched last and acquire-poll the per-b counter that
// score blocks release-increment. Frame-1 copy is fully independent and keeps
// the DRAM/LTS pipes saturated while the latency-bound score slabs stream in.
// ---------------------------------------------------------------------------
__global__ void __launch_bounds__(256) k_phase1(const float* __restrict__ x,
                                                const float* __restrict__ cls,
                                                float* __restrict__ out)
{
    __shared__ __align__(16) float sbuf[CCHUNK * NP + 64];  // 23.3 KB, role-aliased
    const int bid = blockIdx.x;
    const int tid = threadIdx.x;

    if (bid < N_SCORE) {
        // ================= score path (16 c x 360 p partial dots) ==========
        const int b  = bid >> 6;          // 0..15
        const int cs = bid & 63;          // 0..63

        float* xs    = sbuf;              // [CCHUNK*NP]
        float* cls_s = sbuf + CCHUNK * NP;

        const float* xbase = x + ((size_t)b * NC + (size_t)cs * CCHUNK) * TSTRIDE; // t=0
        const unsigned int s_dst = (unsigned int)__cvta_generic_to_shared(xs);

        // 1440 16-byte async copies; q = c*90 + off -> smem contiguous
        for (int q = tid; q < CCHUNK * (NP / 4); q += 256) {
            const int c   = q / (NP / 4);
            const int off = q - c * (NP / 4);
            const float* src = xbase + (size_t)c * TSTRIDE + off * 4;
            asm volatile("cp.async.cg.shared.global [%0], [%1], 16;\n"
                         :: "r"(s_dst + q * 16), "l"(src));
        }
        if (tid < CCHUNK)
            cls_s[tid] = cls[b * (NT * NC) + cs * CCHUNK + tid];   // t=0 cls

        asm volatile("cp.async.commit_group;\ncp.async.wait_group 0;\n" ::: "memory");
        __syncthreads();

        if (tid < NP / 4) {   // 90 active p-quads
            float4 acc = make_float4(0.f, 0.f, 0.f, 0.f);
            #pragma unroll
            for (int c = 0; c < CCHUNK; ++c) {
                const float4 v = *reinterpret_cast<const float4*>(&xs[c * NP + tid * 4]);
                const float  w = cls_s[c];
                acc.x = fmaf(w, v.x, acc.x);
                acc.y = fmaf(w, v.y, acc.y);
                acc.z = fmaf(w, v.z, acc.z);
                acc.w = fmaf(w, v.w, acc.w);
            }
            *reinterpret_cast<float4*>(&g_spart[b][cs][tid * 4]) = acc;
        }
        __syncthreads();   // all g_spart stores ordered before the release below
        if (tid == 0)
            asm volatile("red.release.gpu.global.add.s32 [%0], 1;"
                         :: "l"(&g_cnt[b * 32]) : "memory");
    }
    else if (bid < BID_SORT) {
        // ================= frame-1 transpose copy (independent) ============
        const int idx = bid - BID_COPY1;     // 0..1535
        const int ct  = idx & 31;            // c tile of 32
        const int rem = idx >> 5;
        const int pt  = rem % 3;             // p tile of 128
        const int b   = rem / 3;             // 0..15

        float* tiles = sbuf;                 // [4][1057], stride 1057 == 1 (mod 32)
        const float* xbase = x + ((size_t)b * NC + ct * 32) * TSTRIDE + NP; // t=1
        const int pbase = pt * 128;

        #pragma unroll
        for (int i = 0; i < 4; ++i) {
            const int s  = tid + 256 * i;
            const int cl = s >> 5;           // 0..31
            const int pq = s & 31;           // 0..31
            const int p  = pbase + pq * 4;
            if (p < NP) {
                const float4 v = *reinterpret_cast<const float4*>(
                    xbase + (size_t)cl * TSTRIDE + p);
                const int sidx = cl * 33 + pq;
                tiles[0 * 1057 + sidx] = v.x;
                tiles[1 * 1057 + sidx] = v.y;
                tiles[2 * 1057 + sidx] = v.z;
                tiles[3 * 1057 + sidx] = v.w;
            }
        }
        __syncthreads();

        const size_t obase = (size_t)b * ROWS * NC;
        #pragma unroll
        for (int i = 0; i < 4; ++i) {
            const int s  = tid + 256 * i;
            const int cq = s & 7;            // 0..7
            const int pl = s >> 3;           // 0..127
            const int pg = pbase + pl;
            if (pg < NP) {
                const int row = 122 + pg;
                const int j  = pl & 3;
                const int pq = pl >> 2;
                float4 w;
                w.x = tiles[j * 1057 + (4 * cq + 0) * 33 + pq];
                w.y = tiles[j * 1057 + (4 * cq + 1) * 33 + pq];
                w.z = tiles[j * 1057 + (4 * cq + 2) * 33 + pq];
                w.w = tiles[j * 1057 + (4 * cq + 3) * 33 + pq];
                *reinterpret_cast<float4*>(
                    out + obase + (size_t)row * NC + ct * 32 + cq * 4) = w;
            }
        }
    }
    else {
        // ================= sort path (dispatched last) =====================
        const int b = bid - BID_SORT;
        float* sv = sbuf;                                 // [512]
        int*   si = reinterpret_cast<int*>(sbuf + 512);   // [512]

        if (tid == 0) {
            int v;
            do {
                __nanosleep(64);
                asm volatile("ld.acquire.gpu.global.s32 %0, [%1];"
                             : "=r"(v) : "l"(&g_cnt[b * 32]) : "memory");
            } while (v < CSPLIT);
        }
        __syncthreads();   // acquire ordering propagates to all threads via bar

        for (int e = tid; e < 512; e += 256) {
            float vsum = -CUDART_INF_F;
            if (e < NP) {
                float a0 = 0.f, a1 = 0.f, a2 = 0.f, a3 = 0.f;
                #pragma unroll
                for (int k = 0; k < CSPLIT; k += 4) {
                    a0 += g_spart[b][k + 0][e];
                    a1 += g_spart[b][k + 1][e];
                    a2 += g_spart[b][k + 2][e];
                    a3 += g_spart[b][k + 3][e];
                }
                vsum = (a0 + a1) + (a2 + a3);
            }
            sv[e] = vsum;
            si[e] = e;
        }
        __syncthreads();

        // bitonic sort 512 (desc score, asc idx tiebreak = lax.top_k semantics)
        for (int k = 2; k <= 512; k <<= 1) {
            for (int j = k >> 1; j > 0; j >>= 1) {
                const int l = 2 * tid - (tid & (j - 1));   // l & j == 0
                const int m = l | j;
                const float a = sv[l], c = sv[m];
                const int   ia = si[l], ic = si[m];
                const bool a_after = (a < c) || (a == c && ia > ic);
                const bool dir_desc = ((l & k) == 0);
                if (dir_desc ? a_after : !a_after) {
                    sv[l] = c; sv[m] = a; si[l] = ic; si[m] = ia;
                }
                __syncthreads();
            }
        }

        for (int p = tid; p < NP; p += 256) g_posmap[b][p] = -1;
        __syncthreads();
        if (tid < NK) g_posmap[b][si[tid]] = 1 + tid;

        // cls rows: row 0 = cls[b,0,:], row 121 = cls[b,1,:]
        const size_t obase = (size_t)b * ROWS * NC;
        const float4* c4 = reinterpret_cast<const float4*>(cls + (size_t)b * NT * NC);
        float4* o4 = reinterpret_cast<float4*>(out + obase);
        for (int c = tid; c < NC / 4; c += 256) {
            o4[c]                = c4[c];               // row 0   (t=0 cls)
            o4[121 * (NC/4) + c] = c4[(NC/4) + c];      // row 121 (t=1 cls)
        }
    }
}

// ---------------------------------------------------------------------------
// Phase 2: frame-0 selective transpose copy (posmap ready; f0 reads L2-warm).
// grid (32, 3, 16), block 256. Block (0,0,0) also resets the per-b counters
// for the next graph replay (deterministic: g_cnt is consumed only in phase 1
// of the same replay, which completed before this kernel started).
// ---------------------------------------------------------------------------
__global__ void __launch_bounds__(256) k_copy0(const float* __restrict__ x,
                                               float* __restrict__ out)
{
    const int ct = blockIdx.x;          // 0..31
    const int pt = blockIdx.y;          // 0..2
    const int b  = blockIdx.z;
    const int tid = threadIdx.x;

    if (ct == 0 && pt == 0 && b == 0 && tid < NB)
        g_cnt[tid * 32] = 0;            // reset for next replay

    __shared__ float tiles[4][1057];

    const float* xbase = x + ((size_t)b * NC + ct * 32) * TSTRIDE;  // t=0
    const int pbase = pt * 128;

    #pragma unroll
    for (int i = 0; i < 4; ++i) {
        const int s  = tid + 256 * i;
        const int cl = s >> 5;
        const int pq = s & 31;
        const int p  = pbase + pq * 4;
        if (p < NP) {
            const float4 v = *reinterpret_cast<const float4*>(
                xbase + (size_t)cl * TSTRIDE + p);
            const int idx = cl * 33 + pq;
            tiles[0][idx] = v.x;
            tiles[1][idx] = v.y;
            tiles[2][idx] = v.z;
            tiles[3][idx] = v.w;
        }
    }
    __syncthreads();

    const size_t obase = (size_t)b * ROWS * NC;
    #pragma unroll
    for (int i = 0; i < 4; ++i) {
        const int s  = tid + 256 * i;
        const int cq = s & 7;
        const int pl = s >> 3;
        const int pg = pbase + pl;
        if (pg < NP) {
            const int row = g_posmap[b][pg];
            if (row >= 0) {
                const int j  = pl & 3;
                const int pq = pl >> 2;
                float4 w;
                w.x = tiles[j][(4 * cq + 0) * 33 + pq];
                w.y = tiles[j][(4 * cq + 1) * 33 + pq];
                w.z = tiles[j][(4 * cq + 2) * 33 + pq];
                w.w = tiles[j][(4 * cq + 3) * 33 + pq];
                *reinterpret_cast<float4*>(
                    out + obase + (size_t)row * NC + ct * 32 + cq * 4) = w;
            }
        }
    }
}

// ---------------------------------------------------------------------------
extern "C" void kernel_launch(void* const* d_in, const int* in_sizes, int n_in,
                              void* d_out, int out_size)
{
    const float* x   = (const float*)d_in[0];   // [16,1024,16,12,30]
    const float* cls = (const float*)d_in[1];   // [16,16,1024]
    float* out = (float*)d_out;                 // [16,482,1024]

    k_phase1<<<GRID_P1, 256>>>(x, cls, out);
    k_copy0<<<dim3(32, 3, NB), 256>>>(x, out);
}